// round 10
// baseline (speedup 1.0000x reference)
#include <cuda_runtime.h>
#include <cuda_fp16.h>
#include <cstdint>
#include <cstddef>

#define B_SZ  256
#define C_SZ  10
#define N_CAP 1152
#define DIN   8
#define U_SZ  16

// 94.4 MB fp16 scratch, layout [b][c][q][n] as uint2 (q = u-quad 0..3).
// Fits in GB300's 126MB L2: k1 keeps it resident by streaming x/W with .cs.
__device__ __align__(16) uint2 g_uhat2[(size_t)B_SZ * C_SZ * 4 * N_CAP];

#define FFMA2(d, a, bb, cc) \
    asm("fma.rn.f32x2 %0, %1, %2, %3;" : "=l"(d) : "l"(a), "l"(bb), "l"(cc))
#define DUP2(d, s) \
    asm("mov.b64 %0, {%1, %1};" : "=l"(d) : "r"(s))
#define F2H2(d, lo, hi) \
    asm("cvt.rn.f16x2.f32 %0, %1, %2;" : "=r"(d) : "f"(hi), "f"(lo))

__device__ __forceinline__ __half2 u2h2(unsigned int v) { return *(__half2*)&v; }

// ---------------------------------------------------------------------------
// K1: u_hat -> fp16 [b][c][q][n] uint2.
// Grid (36, 10, 8). 256 thr = 2 b-halves x 32 n x 4 u-quads.
// W slice (8i x 4u) in regs (16 f32x2); x staged in smem (12-word rows).
// x and W loaded with .cs (evict-first) so scratch stores own the L2.
// ---------------------------------------------------------------------------
__global__ __launch_bounds__(256) void k1_uhat(const float* __restrict__ x,
                                               const float* __restrict__ W)
{
    __shared__ float xs[32 * 32 * 12];   // 48KB

    const int n0 = blockIdx.x * 32;
    const int c  = blockIdx.y;
    const int b0 = blockIdx.z * 32;

    for (int t = threadIdx.x; t < 1024; t += 256) {
        const int b = t >> 5, n = t & 31;
        const float4* g = (const float4*)(x + ((size_t)(b0 + b) * N_CAP + (n0 + n)) * DIN);
        float4 v0 = __ldcs(g);
        float4 v1 = __ldcs(g + 1);
        float* d = xs + (b * 32 + n) * 12;
        *(float4*)(d)     = v0;
        *(float4*)(d + 4) = v1;
    }

    const int uq = threadIdx.x & 3;
    const int nl = (threadIdx.x >> 2) & 31;
    const int bl = threadIdx.x >> 7;     // 0..1
    const int n  = n0 + nl;

    unsigned long long wr[16];
    {
        const ulonglong2* Wp = (const ulonglong2*)(W + ((size_t)c * N_CAP + n) * 128);
        #pragma unroll
        for (int i = 0; i < 8; ++i) {
            ulonglong2 w = __ldcs(&Wp[i * 4 + uq]);
            wr[2 * i]     = w.x;     // u pair (4uq, 4uq+1)
            wr[2 * i + 1] = w.y;     // u pair (4uq+2, 4uq+3)
        }
    }
    __syncthreads();

    uint2* op = g_uhat2 +
        (((size_t)(b0 + bl * 16) * C_SZ + c) * 4 + uq) * N_CAP + n;

    #pragma unroll 4
    for (int s = 0; s < 16; ++s) {
        const int b = bl * 16 + s;
        const float* xp = xs + (b * 32 + nl) * 12;
        float4 xa = *(const float4*)(xp);
        float4 xb = *(const float4*)(xp + 4);

        unsigned long long x0, x1, x2, x3, x4, x5, x6, x7;
        DUP2(x0, __float_as_uint(xa.x));  DUP2(x1, __float_as_uint(xa.y));
        DUP2(x2, __float_as_uint(xa.z));  DUP2(x3, __float_as_uint(xa.w));
        DUP2(x4, __float_as_uint(xb.x));  DUP2(x5, __float_as_uint(xb.y));
        DUP2(x6, __float_as_uint(xb.z));  DUP2(x7, __float_as_uint(xb.w));

        unsigned long long a0 = 0ull, a1 = 0ull;
        FFMA2(a0, wr[0],  x0, a0);  FFMA2(a1, wr[1],  x0, a1);
        FFMA2(a0, wr[2],  x1, a0);  FFMA2(a1, wr[3],  x1, a1);
        FFMA2(a0, wr[4],  x2, a0);  FFMA2(a1, wr[5],  x2, a1);
        FFMA2(a0, wr[6],  x3, a0);  FFMA2(a1, wr[7],  x3, a1);
        FFMA2(a0, wr[8],  x4, a0);  FFMA2(a1, wr[9],  x4, a1);
        FFMA2(a0, wr[10], x5, a0);  FFMA2(a1, wr[11], x5, a1);
        FFMA2(a0, wr[12], x6, a0);  FFMA2(a1, wr[13], x6, a1);
        FFMA2(a0, wr[14], x7, a0);  FFMA2(a1, wr[15], x7, a1);

        unsigned int l0, h0, l1, h1;
        asm("mov.b64 {%0, %1}, %2;" : "=r"(l0), "=r"(h0) : "l"(a0));
        asm("mov.b64 {%0, %1}, %2;" : "=r"(l1), "=r"(h1) : "l"(a1));
        __half2 p0 = __floats2half2_rn(__uint_as_float(l0), __uint_as_float(h0));
        __half2 p1 = __floats2half2_rn(__uint_as_float(l1), __uint_as_float(h1));
        uint2 st;
        st.x = *(unsigned int*)&p0;
        st.y = *(unsigned int*)&p1;
        *op = st;                        // default .wb -> stays in L2
        op += (size_t)C_SZ * 4 * N_CAP;
    }
}

// ---------------------------------------------------------------------------
__device__ __forceinline__ float blockReduceSum(float v, float* scratch)
{
    #pragma unroll
    for (int o = 16; o > 0; o >>= 1) v += __shfl_xor_sync(0xffffffffu, v, o);
    if ((threadIdx.x & 31) == 0) scratch[threadIdx.x >> 5] = v;
    __syncthreads();
    float r = 0.f;
    #pragma unroll
    for (int i = 0; i < 8; ++i) r += scratch[i];
    __syncthreads();
    return r;
}

// ---------------------------------------------------------------------------
// K2: routing per (b,c). Grid (C, B), 256 thr, 37.4KB smem, 6 CTAs/SM.
//  prologue: 2 warps per u-quad row stream global->smem (L2 hits),
//            uniform-s0 via HADD2.
//  it=1,2:  fused n-scan: 4 LDS.64 -> HFMA2 dot -> exp -> fp16 HFMA2
//           s-accum (per-thread partials ~5 terms); butterfly in fp32.
// ---------------------------------------------------------------------------
__global__ __launch_bounds__(256, 6) void k2_route(float* __restrict__ outp)
{
    extern __shared__ float sm[];
    unsigned int* uh  = (unsigned int*)sm;            // 4 rows x 2304 words
    float* red  = sm + 4 * 2304;                      // 128
    float* red2 = red + 128;                          // 8
    unsigned int* w_h = (unsigned int*)(red2 + 8);    // 8 words (16B aligned)

    const int tid = threadIdx.x;
    const int c   = blockIdx.x;
    const int b   = blockIdx.y;
    const int w   = tid >> 5;
    const int g   = tid & 31;
    const int q   = w >> 1;
    const int hf  = w & 1;
    const __half2 z = __float2half2_rn(0.f);

    // ---- prologue: stream row q (half per warp), HADD2 uniform-s0 ----
    {
        const uint4* src = (const uint4*)(g_uhat2 +
                            (((size_t)b * C_SZ + c) * 4 + q) * N_CAP);
        uint4* dst = (uint4*)(uh + q * 2304);
        __half2 t0 = z, t1 = z, t2 = z, t3 = z;
        const int base = hf * 288;
        #pragma unroll
        for (int i = 0; i < 9; ++i) {
            uint4 v = src[base + i * 32 + g];
            dst[base + i * 32 + g] = v;
            t0 = __hadd2(u2h2(v.x), t0);   // n,   u 4q..4q+1
            t1 = __hadd2(u2h2(v.y), t1);   // n,   u 4q+2..4q+3
            t2 = __hadd2(u2h2(v.z), t2);   // n+1, u 4q..4q+1
            t3 = __hadd2(u2h2(v.w), t3);
        }
        float2 f0 = __half22float2(__hadd2(t0, t2));
        float2 f1 = __half22float2(__hadd2(t1, t3));
        float s0 = f0.x, s1 = f0.y, s2 = f1.x, s3 = f1.y;
        #pragma unroll
        for (int o = 16; o > 0; o >>= 1) {
            s0 += __shfl_xor_sync(0xffffffffu, s0, o);
            s1 += __shfl_xor_sync(0xffffffffu, s1, o);
            s2 += __shfl_xor_sync(0xffffffffu, s2, o);
            s3 += __shfl_xor_sync(0xffffffffu, s3, o);
        }
        if (g == 0) {
            red[w * 4 + 0] = s0;  red[w * 4 + 1] = s1;
            red[w * 4 + 2] = s2;  red[w * 4 + 3] = s3;
        }
    }
    __syncthreads();

    float vprev = 0.f;
    if (tid < 16) {
        const int qq = tid >> 2, ii = tid & 3;
        float s_u = (red[(2 * qq) * 4 + ii] + red[(2 * qq + 1) * 4 + ii])
                    * (1.0f / (float)N_CAP);
        float sq = s_u * s_u;
        sq += __shfl_xor_sync(0x0000ffffu, sq, 1, 16);
        sq += __shfl_xor_sync(0x0000ffffu, sq, 2, 16);
        sq += __shfl_xor_sync(0x0000ffffu, sq, 4, 16);
        sq += __shfl_xor_sync(0x0000ffffu, sq, 8, 16);
        float scale = sq / ((1.0f + sq) * sqrtf(sq + 1e-9f));
        vprev = scale * s_u;                     // v0, u = tid
        float vhi = __shfl_down_sync(0x0000ffffu, vprev, 1, 16);
        if ((tid & 1) == 0) {
            unsigned int hw; F2H2(hw, vprev, vhi);
            w_h[tid >> 1] = hw;                  // w_h[j] = (v_2j, v_2j+1)
        }
    }
    __syncthreads();

    #pragma unroll
    for (int it = 1; it < 3; ++it) {
        uint4 wA = *(const uint4*)(w_h);
        uint4 wB = *(const uint4*)(w_h + 4);
        const __half2 w0 = u2h2(wA.x), w1 = u2h2(wA.y);
        const __half2 w2 = u2h2(wA.z), w3 = u2h2(wA.w);
        const __half2 w4 = u2h2(wB.x), w5 = u2h2(wB.y);
        const __half2 w6 = u2h2(wB.z), w7 = u2h2(wB.w);

        __half2 ha[8];
        #pragma unroll
        for (int j = 0; j < 8; ++j) ha[j] = z;
        float ls = 0.f;

        // ---- fused scan: dot(HFMA2) -> exp -> fp16 s-accum ----
        for (int n = tid; n < N_CAP; n += 256) {
            uint2 d0 = *(const uint2*)(uh + 0 * 2304 + 2 * n);
            uint2 d1 = *(const uint2*)(uh + 1 * 2304 + 2 * n);
            uint2 d2 = *(const uint2*)(uh + 2 * 2304 + 2 * n);
            uint2 d3 = *(const uint2*)(uh + 3 * 2304 + 2 * n);

            __half2 aa = __hfma2(u2h2(d0.x), w0, z);
            aa = __hfma2(u2h2(d0.y), w1, aa);
            aa = __hfma2(u2h2(d1.x), w2, aa);
            aa = __hfma2(u2h2(d1.y), w3, aa);
            __half2 ac = __hfma2(u2h2(d2.x), w4, z);
            ac = __hfma2(u2h2(d2.y), w5, ac);
            ac = __hfma2(u2h2(d3.x), w6, ac);
            ac = __hfma2(u2h2(d3.y), w7, ac);
            float2 f = __half22float2(__hadd2(aa, ac));
            float e = __expf(f.x + f.y);
            ls += e;

            unsigned int ew; F2H2(ew, e, e);
            __half2 e2 = u2h2(ew);
            ha[0] = __hfma2(u2h2(d0.x), e2, ha[0]);
            ha[1] = __hfma2(u2h2(d0.y), e2, ha[1]);
            ha[2] = __hfma2(u2h2(d1.x), e2, ha[2]);
            ha[3] = __hfma2(u2h2(d1.y), e2, ha[3]);
            ha[4] = __hfma2(u2h2(d2.x), e2, ha[4]);
            ha[5] = __hfma2(u2h2(d2.y), e2, ha[5]);
            ha[6] = __hfma2(u2h2(d3.x), e2, ha[6]);
            ha[7] = __hfma2(u2h2(d3.y), e2, ha[7]);
        }

        // convert partials to fp32 once
        float acc[16];
        #pragma unroll
        for (int j = 0; j < 8; ++j) {
            float2 f = __half22float2(ha[j]);
            acc[2 * j] = f.x;  acc[2 * j + 1] = f.y;
        }

        // ---- vector-halving butterfly: 16 accums over warp ----
        #pragma unroll
        for (int k = 0; k < 4; ++k) {
            const int o = 1 << k;
            const int h = 8 >> k;
            const bool hi = (g >> k) & 1;
            #pragma unroll
            for (int j = 0; j < h; ++j) {
                float send = hi ? acc[j] : acc[j + h];
                float r = __shfl_xor_sync(0xffffffffu, send, o);
                acc[j] = (hi ? acc[j + h] : acc[j]) + r;
            }
        }
        acc[0] += __shfl_xor_sync(0xffffffffu, acc[0], 16);
        const int u_own = ((g & 1) << 3) | (((g >> 1) & 1) << 2)
                        | (((g >> 2) & 1) << 1) | ((g >> 3) & 1);
        if (g < 16) red[w * 16 + u_own] = acc[0];

        float inv = 1.0f / blockReduceSum(ls, red2);  // syncs publish red

        // ---- squash (u = tid) ----
        if (tid < 16) {
            float s_u = 0.f;
            #pragma unroll
            for (int ww = 0; ww < 8; ++ww) s_u += red[ww * 16 + tid];
            s_u *= inv;
            float sq = s_u * s_u;
            sq += __shfl_xor_sync(0x0000ffffu, sq, 1, 16);
            sq += __shfl_xor_sync(0x0000ffffu, sq, 2, 16);
            sq += __shfl_xor_sync(0x0000ffffu, sq, 4, 16);
            sq += __shfl_xor_sync(0x0000ffffu, sq, 8, 16);
            float scale = sq / ((1.0f + sq) * sqrtf(sq + 1e-9f));
            float vcur = scale * s_u;
            if (it == 1) {
                float wn = vprev + vcur;          // b2 weights via linearity
                float whi = __shfl_down_sync(0x0000ffffu, wn, 1, 16);
                if ((tid & 1) == 0) {
                    unsigned int hw; F2H2(hw, wn, whi);
                    w_h[tid >> 1] = hw;
                }
            } else {
                outp[((size_t)b * C_SZ + c) * U_SZ + tid] = vcur;
            }
        }
        __syncthreads();
    }
}

// ---------------------------------------------------------------------------
extern "C" void kernel_launch(void* const* d_in, const int* in_sizes, int n_in,
                              void* d_out, int out_size)
{
    const float* x = (const float*)d_in[0];
    const float* W = (const float*)d_in[1];
    if (n_in >= 2 && in_sizes[0] == C_SZ * N_CAP * DIN * U_SZ &&
        in_sizes[1] == B_SZ * N_CAP * DIN) {
        const float* t = x; x = W; W = t;
    }

    const size_t smem2 =
        (size_t)(4 * 2304 + 128 + 8 + 8) * sizeof(float);   // 37,440B
    cudaFuncSetAttribute(k2_route, cudaFuncAttributeMaxDynamicSharedMemorySize,
                         (int)smem2);

    k1_uhat<<<dim3(N_CAP / 32, C_SZ, B_SZ / 32), 256>>>(x, W);
    k2_route<<<dim3(C_SZ, B_SZ), 256, smem2>>>((float*)d_out);
}

// round 11
// speedup vs baseline: 1.3482x; 1.3482x over previous
#include <cuda_runtime.h>
#include <cuda_fp16.h>
#include <cstdint>
#include <cstddef>

#define B_SZ    256
#define C_SZ    10
#define N_CAP   1152
#define DIN     8
#define U_SZ    16
#define B_CHUNK 128   // 2 chunks: 47.2MB scratch/chunk stays L2-resident

// 94.4 MB fp16 scratch, layout [b][c][q][n] as uint2 (q = u-quad 0..3).
__device__ __align__(16) uint2 g_uhat2[(size_t)B_SZ * C_SZ * 4 * N_CAP];

#define FFMA2(d, a, bb, cc) \
    asm("fma.rn.f32x2 %0, %1, %2, %3;" : "=l"(d) : "l"(a), "l"(bb), "l"(cc))
#define DUP2(d, s) \
    asm("mov.b64 %0, {%1, %1};" : "=l"(d) : "r"(s))
#define F2H2(d, lo, hi) \
    asm("cvt.rn.f16x2.f32 %0, %1, %2;" : "=r"(d) : "f"(hi), "f"(lo))

__device__ __forceinline__ __half2 u2h2(unsigned int v) { return *(__half2*)&v; }

// ---------------------------------------------------------------------------
// K1 (R8-identical compute): u_hat -> fp16 [b][c][q][n] uint2.
// Grid (36, 10, B_CHUNK/32). 256 thr = 2 b-halves x 32 n x 4 u-quads.
// W slice (8i x 4u) in regs (16 f32x2); x staged in smem (12-word rows).
// Plain (cached) loads — x/W are hot in L2 across c/z blocks.
// ---------------------------------------------------------------------------
__global__ __launch_bounds__(256) void k1_uhat(const float* __restrict__ x,
                                               const float* __restrict__ W,
                                               int bbase)
{
    __shared__ float xs[32 * 32 * 12];   // 48KB

    const int n0 = blockIdx.x * 32;
    const int c  = blockIdx.y;
    const int b0 = blockIdx.z * 32;      // local within chunk

    for (int t = threadIdx.x; t < 1024; t += 256) {
        const int b = t >> 5, n = t & 31;
        const float4* g = (const float4*)(x + ((size_t)(b0 + b) * N_CAP + (n0 + n)) * DIN);
        float4 v0 = g[0], v1 = g[1];
        float* d = xs + (b * 32 + n) * 12;
        *(float4*)(d)     = v0;
        *(float4*)(d + 4) = v1;
    }

    const int uq = threadIdx.x & 3;
    const int nl = (threadIdx.x >> 2) & 31;
    const int bl = threadIdx.x >> 7;     // 0..1
    const int n  = n0 + nl;

    unsigned long long wr[16];
    {
        const ulonglong2* Wp = (const ulonglong2*)(W + ((size_t)c * N_CAP + n) * 128);
        #pragma unroll
        for (int i = 0; i < 8; ++i) {
            ulonglong2 w = Wp[i * 4 + uq];
            wr[2 * i]     = w.x;     // u pair (4uq, 4uq+1)
            wr[2 * i + 1] = w.y;     // u pair (4uq+2, 4uq+3)
        }
    }
    __syncthreads();

    uint2* op = g_uhat2 +
        (((size_t)(bbase + b0 + bl * 16) * C_SZ + c) * 4 + uq) * N_CAP + n;

    #pragma unroll 4
    for (int s = 0; s < 16; ++s) {
        const int b = bl * 16 + s;
        const float* xp = xs + (b * 32 + nl) * 12;
        float4 xa = *(const float4*)(xp);
        float4 xb = *(const float4*)(xp + 4);

        unsigned long long x0, x1, x2, x3, x4, x5, x6, x7;
        DUP2(x0, __float_as_uint(xa.x));  DUP2(x1, __float_as_uint(xa.y));
        DUP2(x2, __float_as_uint(xa.z));  DUP2(x3, __float_as_uint(xa.w));
        DUP2(x4, __float_as_uint(xb.x));  DUP2(x5, __float_as_uint(xb.y));
        DUP2(x6, __float_as_uint(xb.z));  DUP2(x7, __float_as_uint(xb.w));

        unsigned long long a0 = 0ull, a1 = 0ull;
        FFMA2(a0, wr[0],  x0, a0);  FFMA2(a1, wr[1],  x0, a1);
        FFMA2(a0, wr[2],  x1, a0);  FFMA2(a1, wr[3],  x1, a1);
        FFMA2(a0, wr[4],  x2, a0);  FFMA2(a1, wr[5],  x2, a1);
        FFMA2(a0, wr[6],  x3, a0);  FFMA2(a1, wr[7],  x3, a1);
        FFMA2(a0, wr[8],  x4, a0);  FFMA2(a1, wr[9],  x4, a1);
        FFMA2(a0, wr[10], x5, a0);  FFMA2(a1, wr[11], x5, a1);
        FFMA2(a0, wr[12], x6, a0);  FFMA2(a1, wr[13], x6, a1);
        FFMA2(a0, wr[14], x7, a0);  FFMA2(a1, wr[15], x7, a1);

        unsigned int l0, h0, l1, h1;
        asm("mov.b64 {%0, %1}, %2;" : "=r"(l0), "=r"(h0) : "l"(a0));
        asm("mov.b64 {%0, %1}, %2;" : "=r"(l1), "=r"(h1) : "l"(a1));
        __half2 p0 = __floats2half2_rn(__uint_as_float(l0), __uint_as_float(h0));
        __half2 p1 = __floats2half2_rn(__uint_as_float(l1), __uint_as_float(h1));
        uint2 st;
        st.x = *(unsigned int*)&p0;      // u 4uq, 4uq+1
        st.y = *(unsigned int*)&p1;      // u 4uq+2, 4uq+3
        *op = st;                        // one STG.64 (default .wb -> L2)
        op += (size_t)C_SZ * 4 * N_CAP;
    }
}

// ---------------------------------------------------------------------------
__device__ __forceinline__ float blockReduceSum(float v, float* scratch)
{
    #pragma unroll
    for (int o = 16; o > 0; o >>= 1) v += __shfl_xor_sync(0xffffffffu, v, o);
    if ((threadIdx.x & 31) == 0) scratch[threadIdx.x >> 5] = v;
    __syncthreads();
    float r = 0.f;
    #pragma unroll
    for (int i = 0; i < 8; ++i) r += scratch[i];
    __syncthreads();
    return r;
}

// ---------------------------------------------------------------------------
// K2 (R8-identical): routing per (b,c). Grid (C, B_CHUNK), 256 thr,
// 37.4KB smem, 5 CTAs/SM. Reads chunk scratch while it is L2-hot.
//  prologue: 2 warps per u-quad row stream global->smem, fused uniform-s0.
//  it=1,2:  fused n-scan: 4 LDS.64 -> HFMA2 dot -> exp -> fp32 s-accum
//           into acc[16]; vector-halving butterfly; squash. No c_arr.
// ---------------------------------------------------------------------------
__global__ __launch_bounds__(256, 5) void k2_route(float* __restrict__ outp,
                                                   int bbase)
{
    extern __shared__ float sm[];
    unsigned int* uh  = (unsigned int*)sm;            // 4 rows x 2304 words
    float* red  = sm + 4 * 2304;                      // 128
    float* red2 = red + 128;                          // 8
    unsigned int* w_h = (unsigned int*)(red2 + 8);    // 8 words (16B aligned)

    const int tid = threadIdx.x;
    const int c   = blockIdx.x;
    const int b   = blockIdx.y;          // local within chunk
    const int w   = tid >> 5;
    const int g   = tid & 31;
    const int q   = w >> 1;
    const int hf  = w & 1;

    // ---- prologue: stream row q (half per warp), fused uniform-s0 ----
    {
        const uint4* src = (const uint4*)(g_uhat2 +
                            (((size_t)(bbase + b) * C_SZ + c) * 4 + q) * N_CAP);
        uint4* dst = (uint4*)(uh + q * 2304);
        float s0 = 0.f, s1 = 0.f, s2 = 0.f, s3 = 0.f;
        const int base = hf * 288;
        #pragma unroll
        for (int i = 0; i < 9; ++i) {
            uint4 v = src[base + i * 32 + g];      // 2 n of quad q
            dst[base + i * 32 + g] = v;
            float2 a  = __half22float2(u2h2(v.x)); // n,   u 4q..4q+1
            float2 bb = __half22float2(u2h2(v.y)); // n,   u 4q+2..4q+3
            float2 cc = __half22float2(u2h2(v.z)); // n+1
            float2 dd = __half22float2(u2h2(v.w));
            s0 += a.x + cc.x;  s1 += a.y + cc.y;
            s2 += bb.x + dd.x; s3 += bb.y + dd.y;
        }
        #pragma unroll
        for (int o = 16; o > 0; o >>= 1) {
            s0 += __shfl_xor_sync(0xffffffffu, s0, o);
            s1 += __shfl_xor_sync(0xffffffffu, s1, o);
            s2 += __shfl_xor_sync(0xffffffffu, s2, o);
            s3 += __shfl_xor_sync(0xffffffffu, s3, o);
        }
        if (g == 0) {
            red[w * 4 + 0] = s0;  red[w * 4 + 1] = s1;
            red[w * 4 + 2] = s2;  red[w * 4 + 3] = s3;
        }
    }
    __syncthreads();

    float vprev = 0.f;
    if (tid < 16) {
        const int qq = tid >> 2, ii = tid & 3;
        float s_u = (red[(2 * qq) * 4 + ii] + red[(2 * qq + 1) * 4 + ii])
                    * (1.0f / (float)N_CAP);
        float sq = s_u * s_u;
        sq += __shfl_xor_sync(0x0000ffffu, sq, 1, 16);
        sq += __shfl_xor_sync(0x0000ffffu, sq, 2, 16);
        sq += __shfl_xor_sync(0x0000ffffu, sq, 4, 16);
        sq += __shfl_xor_sync(0x0000ffffu, sq, 8, 16);
        float scale = sq / ((1.0f + sq) * sqrtf(sq + 1e-9f));
        vprev = scale * s_u;                     // v0, u = tid
        float vhi = __shfl_down_sync(0x0000ffffu, vprev, 1, 16);
        if ((tid & 1) == 0) {
            unsigned int hw; F2H2(hw, vprev, vhi);
            w_h[tid >> 1] = hw;                  // w_h[j] = (v_2j, v_2j+1)
        }
    }
    __syncthreads();

    #pragma unroll
    for (int it = 1; it < 3; ++it) {
        uint4 wA = *(const uint4*)(w_h);
        uint4 wB = *(const uint4*)(w_h + 4);
        const __half2 w0 = u2h2(wA.x), w1 = u2h2(wA.y);
        const __half2 w2 = u2h2(wA.z), w3 = u2h2(wA.w);
        const __half2 w4 = u2h2(wB.x), w5 = u2h2(wB.y);
        const __half2 w6 = u2h2(wB.z), w7 = u2h2(wB.w);
        const __half2 z = __float2half2_rn(0.f);

        float acc[16];
        #pragma unroll
        for (int u = 0; u < 16; ++u) acc[u] = 0.f;
        float ls = 0.f;

        // ---- fused scan: dot(HFMA2) -> exp -> fp32 s-accum ----
        for (int n = tid; n < N_CAP; n += 256) {
            uint2 d0 = *(const uint2*)(uh + 0 * 2304 + 2 * n);
            uint2 d1 = *(const uint2*)(uh + 1 * 2304 + 2 * n);
            uint2 d2 = *(const uint2*)(uh + 2 * 2304 + 2 * n);
            uint2 d3 = *(const uint2*)(uh + 3 * 2304 + 2 * n);

            __half2 aa = __hfma2(u2h2(d0.x), w0, z);
            aa = __hfma2(u2h2(d0.y), w1, aa);
            aa = __hfma2(u2h2(d1.x), w2, aa);
            aa = __hfma2(u2h2(d1.y), w3, aa);
            __half2 ac = __hfma2(u2h2(d2.x), w4, z);
            ac = __hfma2(u2h2(d2.y), w5, ac);
            ac = __hfma2(u2h2(d3.x), w6, ac);
            ac = __hfma2(u2h2(d3.y), w7, ac);
            float dot = (__low2float(aa) + __high2float(aa))
                      + (__low2float(ac) + __high2float(ac));
            float e = __expf(dot);
            ls += e;

            float2 v;
            v = __half22float2(u2h2(d0.x));
            acc[0]  = fmaf(e, v.x, acc[0]);   acc[1]  = fmaf(e, v.y, acc[1]);
            v = __half22float2(u2h2(d0.y));
            acc[2]  = fmaf(e, v.x, acc[2]);   acc[3]  = fmaf(e, v.y, acc[3]);
            v = __half22float2(u2h2(d1.x));
            acc[4]  = fmaf(e, v.x, acc[4]);   acc[5]  = fmaf(e, v.y, acc[5]);
            v = __half22float2(u2h2(d1.y));
            acc[6]  = fmaf(e, v.x, acc[6]);   acc[7]  = fmaf(e, v.y, acc[7]);
            v = __half22float2(u2h2(d2.x));
            acc[8]  = fmaf(e, v.x, acc[8]);   acc[9]  = fmaf(e, v.y, acc[9]);
            v = __half22float2(u2h2(d2.y));
            acc[10] = fmaf(e, v.x, acc[10]);  acc[11] = fmaf(e, v.y, acc[11]);
            v = __half22float2(u2h2(d3.x));
            acc[12] = fmaf(e, v.x, acc[12]);  acc[13] = fmaf(e, v.y, acc[13]);
            v = __half22float2(u2h2(d3.y));
            acc[14] = fmaf(e, v.x, acc[14]);  acc[15] = fmaf(e, v.y, acc[15]);
        }

        // ---- vector-halving butterfly: 16 accums over warp ----
        #pragma unroll
        for (int k = 0; k < 4; ++k) {
            const int o = 1 << k;
            const int h = 8 >> k;
            const bool hi = (g >> k) & 1;
            #pragma unroll
            for (int j = 0; j < h; ++j) {
                float send = hi ? acc[j] : acc[j + h];
                float r = __shfl_xor_sync(0xffffffffu, send, o);
                acc[j] = (hi ? acc[j + h] : acc[j]) + r;
            }
        }
        acc[0] += __shfl_xor_sync(0xffffffffu, acc[0], 16);
        const int u_own = ((g & 1) << 3) | (((g >> 1) & 1) << 2)
                        | (((g >> 2) & 1) << 1) | ((g >> 3) & 1);
        if (g < 16) red[w * 16 + u_own] = acc[0];

        float inv = 1.0f / blockReduceSum(ls, red2);  // syncs publish red

        // ---- squash (u = tid) ----
        if (tid < 16) {
            float s_u = 0.f;
            #pragma unroll
            for (int ww = 0; ww < 8; ++ww) s_u += red[ww * 16 + tid];
            s_u *= inv;
            float sq = s_u * s_u;
            sq += __shfl_xor_sync(0x0000ffffu, sq, 1, 16);
            sq += __shfl_xor_sync(0x0000ffffu, sq, 2, 16);
            sq += __shfl_xor_sync(0x0000ffffu, sq, 4, 16);
            sq += __shfl_xor_sync(0x0000ffffu, sq, 8, 16);
            float scale = sq / ((1.0f + sq) * sqrtf(sq + 1e-9f));
            float vcur = scale * s_u;
            if (it == 1) {
                float wn = vprev + vcur;          // b2 weights via linearity
                float whi = __shfl_down_sync(0x0000ffffu, wn, 1, 16);
                if ((tid & 1) == 0) {
                    unsigned int hw; F2H2(hw, wn, whi);
                    w_h[tid >> 1] = hw;
                }
            } else {
                outp[((size_t)b * C_SZ + c) * U_SZ + tid] = vcur;
            }
        }
        __syncthreads();
    }
}

// ---------------------------------------------------------------------------
extern "C" void kernel_launch(void* const* d_in, const int* in_sizes, int n_in,
                              void* d_out, int out_size)
{
    const float* x = (const float*)d_in[0];
    const float* W = (const float*)d_in[1];
    if (n_in >= 2 && in_sizes[0] == C_SZ * N_CAP * DIN * U_SZ &&
        in_sizes[1] == B_SZ * N_CAP * DIN) {
        const float* t = x; x = W; W = t;
    }

    const size_t smem2 =
        (size_t)(4 * 2304 + 128 + 8 + 8) * sizeof(float);   // 37,440B
    cudaFuncSetAttribute(k2_route, cudaFuncAttributeMaxDynamicSharedMemorySize,
                         (int)smem2);

    for (int ch = 0; ch < B_SZ / B_CHUNK; ++ch) {
        const int bbase = ch * B_CHUNK;
        const float* xc = x + (size_t)bbase * N_CAP * DIN;
        float* oc = (float*)d_out + (size_t)bbase * C_SZ * U_SZ;
        k1_uhat<<<dim3(N_CAP / 32, C_SZ, B_CHUNK / 32), 256>>>(xc, W, bbase);
        k2_route<<<dim3(C_SZ, B_CHUNK), 256, smem2>>>(oc, bbase);
    }
}

// round 13
// speedup vs baseline: 1.4157x; 1.0501x over previous
#include <cuda_runtime.h>
#include <cuda_fp16.h>
#include <cstdint>
#include <cstddef>

#define B_SZ    256
#define C_SZ    10
#define N_CAP   1152
#define DIN     8
#define U_SZ    16
#define B_CHUNK 128

// 94.4 MB fp16 scratch, layout [b][c][q][n] as uint2 (q = u-quad 0..3).
__device__ __align__(16) uint2 g_uhat2[(size_t)B_SZ * C_SZ * 4 * N_CAP];

#define FFMA2(d, a, bb, cc) \
    asm("fma.rn.f32x2 %0, %1, %2, %3;" : "=l"(d) : "l"(a), "l"(bb), "l"(cc))
#define DUP2(d, s) \
    asm("mov.b64 %0, {%1, %1};" : "=l"(d) : "r"(s))
#define F2H2(d, lo, hi) \
    asm("cvt.rn.f16x2.f32 %0, %1, %2;" : "=r"(d) : "f"(hi), "f"(lo))

__device__ __forceinline__ __half2 u2h2(unsigned int v) { return *(__half2*)&v; }

// ---------------------------------------------------------------------------
// K1 (R11-identical, measured 14.3us/chunk): u_hat -> fp16 [b][c][q][n].
// Grid (36, 10, B_CHUNK/32). 256 thr = 2 b-halves x 32 n x 4 u-quads.
// W slice (8i x 4u) in regs (16 f32x2); x staged in smem (12-word rows).
// ---------------------------------------------------------------------------
__global__ __launch_bounds__(256) void k1_uhat(const float* __restrict__ x,
                                               const float* __restrict__ W,
                                               int bbase)
{
    __shared__ float xs[32 * 32 * 12];   // 48KB

    const int n0 = blockIdx.x * 32;
    const int c  = blockIdx.y;
    const int b0 = blockIdx.z * 32;      // local within chunk

    for (int t = threadIdx.x; t < 1024; t += 256) {
        const int b = t >> 5, n = t & 31;
        const float4* g = (const float4*)(x + ((size_t)(b0 + b) * N_CAP + (n0 + n)) * DIN);
        float4 v0 = g[0], v1 = g[1];
        float* d = xs + (b * 32 + n) * 12;
        *(float4*)(d)     = v0;
        *(float4*)(d + 4) = v1;
    }

    const int uq = threadIdx.x & 3;
    const int nl = (threadIdx.x >> 2) & 31;
    const int bl = threadIdx.x >> 7;     // 0..1
    const int n  = n0 + nl;

    unsigned long long wr[16];
    {
        const ulonglong2* Wp = (const ulonglong2*)(W + ((size_t)c * N_CAP + n) * 128);
        #pragma unroll
        for (int i = 0; i < 8; ++i) {
            ulonglong2 w = Wp[i * 4 + uq];
            wr[2 * i]     = w.x;     // u pair (4uq, 4uq+1)
            wr[2 * i + 1] = w.y;     // u pair (4uq+2, 4uq+3)
        }
    }
    __syncthreads();

    uint2* op = g_uhat2 +
        (((size_t)(bbase + b0 + bl * 16) * C_SZ + c) * 4 + uq) * N_CAP + n;

    #pragma unroll 4
    for (int s = 0; s < 16; ++s) {
        const int b = bl * 16 + s;
        const float* xp = xs + (b * 32 + nl) * 12;
        float4 xa = *(const float4*)(xp);
        float4 xb = *(const float4*)(xp + 4);

        unsigned long long x0, x1, x2, x3, x4, x5, x6, x7;
        DUP2(x0, __float_as_uint(xa.x));  DUP2(x1, __float_as_uint(xa.y));
        DUP2(x2, __float_as_uint(xa.z));  DUP2(x3, __float_as_uint(xa.w));
        DUP2(x4, __float_as_uint(xb.x));  DUP2(x5, __float_as_uint(xb.y));
        DUP2(x6, __float_as_uint(xb.z));  DUP2(x7, __float_as_uint(xb.w));

        unsigned long long a0 = 0ull, a1 = 0ull;
        FFMA2(a0, wr[0],  x0, a0);  FFMA2(a1, wr[1],  x0, a1);
        FFMA2(a0, wr[2],  x1, a0);  FFMA2(a1, wr[3],  x1, a1);
        FFMA2(a0, wr[4],  x2, a0);  FFMA2(a1, wr[5],  x2, a1);
        FFMA2(a0, wr[6],  x3, a0);  FFMA2(a1, wr[7],  x3, a1);
        FFMA2(a0, wr[8],  x4, a0);  FFMA2(a1, wr[9],  x4, a1);
        FFMA2(a0, wr[10], x5, a0);  FFMA2(a1, wr[11], x5, a1);
        FFMA2(a0, wr[12], x6, a0);  FFMA2(a1, wr[13], x6, a1);
        FFMA2(a0, wr[14], x7, a0);  FFMA2(a1, wr[15], x7, a1);

        unsigned int l0, h0, l1, h1;
        asm("mov.b64 {%0, %1}, %2;" : "=r"(l0), "=r"(h0) : "l"(a0));
        asm("mov.b64 {%0, %1}, %2;" : "=r"(l1), "=r"(h1) : "l"(a1));
        __half2 p0 = __floats2half2_rn(__uint_as_float(l0), __uint_as_float(h0));
        __half2 p1 = __floats2half2_rn(__uint_as_float(l1), __uint_as_float(h1));
        uint2 st;
        st.x = *(unsigned int*)&p0;
        st.y = *(unsigned int*)&p1;
        *op = st;                        // one STG.64 (default .wb -> L2)
        op += (size_t)C_SZ * 4 * N_CAP;
    }
}

// ---------------------------------------------------------------------------
__device__ __forceinline__ float blockReduceSum(float v, float* scratch)
{
    #pragma unroll
    for (int o = 16; o > 0; o >>= 1) v += __shfl_xor_sync(0xffffffffu, v, o);
    if ((threadIdx.x & 31) == 0) scratch[threadIdx.x >> 5] = v;
    __syncthreads();
    float r = 0.f;
    #pragma unroll
    for (int i = 0; i < 8; ++i) r += scratch[i];
    __syncthreads();
    return r;
}

// ---------------------------------------------------------------------------
// K2 (R8-identical compute, measured 32.2us with forward-b): routing per
// (b,c). Grid (C, B) single launch, 256 thr, 37.4KB smem, 5 CTAs/SM.
// b traversed in REVERSE so the first CTAs read the scratch k1 wrote last
// (still L2-resident); reverse streaming is LRU-friendly for the rest.
// ---------------------------------------------------------------------------
__global__ __launch_bounds__(256, 5) void k2_route(float* __restrict__ outp)
{
    extern __shared__ float sm[];
    unsigned int* uh  = (unsigned int*)sm;            // 4 rows x 2304 words
    float* red  = sm + 4 * 2304;                      // 128
    float* red2 = red + 128;                          // 8
    unsigned int* w_h = (unsigned int*)(red2 + 8);    // 8 words (16B aligned)

    const int tid = threadIdx.x;
    const int c   = blockIdx.x;
    const int b   = (B_SZ - 1) - blockIdx.y;          // reversed traversal
    const int w   = tid >> 5;
    const int g   = tid & 31;
    const int q   = w >> 1;
    const int hf  = w & 1;

    // ---- prologue: stream row q (half per warp), fused uniform-s0 ----
    {
        const uint4* src = (const uint4*)(g_uhat2 +
                            (((size_t)b * C_SZ + c) * 4 + q) * N_CAP);
        uint4* dst = (uint4*)(uh + q * 2304);
        float s0 = 0.f, s1 = 0.f, s2 = 0.f, s3 = 0.f;
        const int base = hf * 288;
        #pragma unroll
        for (int i = 0; i < 9; ++i) {
            uint4 v = src[base + i * 32 + g];      // 2 n of quad q
            dst[base + i * 32 + g] = v;
            float2 a  = __half22float2(u2h2(v.x)); // n,   u 4q..4q+1
            float2 bb = __half22float2(u2h2(v.y)); // n,   u 4q+2..4q+3
            float2 cc = __half22float2(u2h2(v.z)); // n+1
            float2 dd = __half22float2(u2h2(v.w));
            s0 += a.x + cc.x;  s1 += a.y + cc.y;
            s2 += bb.x + dd.x; s3 += bb.y + dd.y;
        }
        #pragma unroll
        for (int o = 16; o > 0; o >>= 1) {
            s0 += __shfl_xor_sync(0xffffffffu, s0, o);
            s1 += __shfl_xor_sync(0xffffffffu, s1, o);
            s2 += __shfl_xor_sync(0xffffffffu, s2, o);
            s3 += __shfl_xor_sync(0xffffffffu, s3, o);
        }
        if (g == 0) {
            red[w * 4 + 0] = s0;  red[w * 4 + 1] = s1;
            red[w * 4 + 2] = s2;  red[w * 4 + 3] = s3;
        }
    }
    __syncthreads();

    float vprev = 0.f;
    if (tid < 16) {
        const int qq = tid >> 2, ii = tid & 3;
        float s_u = (red[(2 * qq) * 4 + ii] + red[(2 * qq + 1) * 4 + ii])
                    * (1.0f / (float)N_CAP);
        float sq = s_u * s_u;
        sq += __shfl_xor_sync(0x0000ffffu, sq, 1, 16);
        sq += __shfl_xor_sync(0x0000ffffu, sq, 2, 16);
        sq += __shfl_xor_sync(0x0000ffffu, sq, 4, 16);
        sq += __shfl_xor_sync(0x0000ffffu, sq, 8, 16);
        float scale = sq / ((1.0f + sq) * sqrtf(sq + 1e-9f));
        vprev = scale * s_u;                     // v0, u = tid
        float vhi = __shfl_down_sync(0x0000ffffu, vprev, 1, 16);
        if ((tid & 1) == 0) {
            unsigned int hw; F2H2(hw, vprev, vhi);
            w_h[tid >> 1] = hw;                  // w_h[j] = (v_2j, v_2j+1)
        }
    }
    __syncthreads();

    #pragma unroll
    for (int it = 1; it < 3; ++it) {
        uint4 wA = *(const uint4*)(w_h);
        uint4 wB = *(const uint4*)(w_h + 4);
        const __half2 w0 = u2h2(wA.x), w1 = u2h2(wA.y);
        const __half2 w2 = u2h2(wA.z), w3 = u2h2(wA.w);
        const __half2 w4 = u2h2(wB.x), w5 = u2h2(wB.y);
        const __half2 w6 = u2h2(wB.z), w7 = u2h2(wB.w);
        const __half2 z = __float2half2_rn(0.f);

        float acc[16];
        #pragma unroll
        for (int u = 0; u < 16; ++u) acc[u] = 0.f;
        float ls = 0.f;

        // ---- fused scan: dot(HFMA2) -> exp -> fp32 s-accum ----
        for (int n = tid; n < N_CAP; n += 256) {
            uint2 d0 = *(const uint2*)(uh + 0 * 2304 + 2 * n);
            uint2 d1 = *(const uint2*)(uh + 1 * 2304 + 2 * n);
            uint2 d2 = *(const uint2*)(uh + 2 * 2304 + 2 * n);
            uint2 d3 = *(const uint2*)(uh + 3 * 2304 + 2 * n);

            __half2 aa = __hfma2(u2h2(d0.x), w0, z);
            aa = __hfma2(u2h2(d0.y), w1, aa);
            aa = __hfma2(u2h2(d1.x), w2, aa);
            aa = __hfma2(u2h2(d1.y), w3, aa);
            __half2 ac = __hfma2(u2h2(d2.x), w4, z);
            ac = __hfma2(u2h2(d2.y), w5, ac);
            ac = __hfma2(u2h2(d3.x), w6, ac);
            ac = __hfma2(u2h2(d3.y), w7, ac);
            float dot = (__low2float(aa) + __high2float(aa))
                      + (__low2float(ac) + __high2float(ac));
            float e = __expf(dot);
            ls += e;

            float2 v;
            v = __half22float2(u2h2(d0.x));
            acc[0]  = fmaf(e, v.x, acc[0]);   acc[1]  = fmaf(e, v.y, acc[1]);
            v = __half22float2(u2h2(d0.y));
            acc[2]  = fmaf(e, v.x, acc[2]);   acc[3]  = fmaf(e, v.y, acc[3]);
            v = __half22float2(u2h2(d1.x));
            acc[4]  = fmaf(e, v.x, acc[4]);   acc[5]  = fmaf(e, v.y, acc[5]);
            v = __half22float2(u2h2(d1.y));
            acc[6]  = fmaf(e, v.x, acc[6]);   acc[7]  = fmaf(e, v.y, acc[7]);
            v = __half22float2(u2h2(d2.x));
            acc[8]  = fmaf(e, v.x, acc[8]);   acc[9]  = fmaf(e, v.y, acc[9]);
            v = __half22float2(u2h2(d2.y));
            acc[10] = fmaf(e, v.x, acc[10]);  acc[11] = fmaf(e, v.y, acc[11]);
            v = __half22float2(u2h2(d3.x));
            acc[12] = fmaf(e, v.x, acc[12]);  acc[13] = fmaf(e, v.y, acc[13]);
            v = __half22float2(u2h2(d3.y));
            acc[14] = fmaf(e, v.x, acc[14]);  acc[15] = fmaf(e, v.y, acc[15]);
        }

        // ---- vector-halving butterfly: 16 accums over warp ----
        #pragma unroll
        for (int k = 0; k < 4; ++k) {
            const int o = 1 << k;
            const int h = 8 >> k;
            const bool hi = (g >> k) & 1;
            #pragma unroll
            for (int j = 0; j < h; ++j) {
                float send = hi ? acc[j] : acc[j + h];
                float r = __shfl_xor_sync(0xffffffffu, send, o);
                acc[j] = (hi ? acc[j + h] : acc[j]) + r;
            }
        }
        acc[0] += __shfl_xor_sync(0xffffffffu, acc[0], 16);
        const int u_own = ((g & 1) << 3) | (((g >> 1) & 1) << 2)
                        | (((g >> 2) & 1) << 1) | ((g >> 3) & 1);
        if (g < 16) red[w * 16 + u_own] = acc[0];

        float inv = 1.0f / blockReduceSum(ls, red2);  // syncs publish red

        // ---- squash (u = tid) ----
        if (tid < 16) {
            float s_u = 0.f;
            #pragma unroll
            for (int ww = 0; ww < 8; ++ww) s_u += red[ww * 16 + tid];
            s_u *= inv;
            float sq = s_u * s_u;
            sq += __shfl_xor_sync(0x0000ffffu, sq, 1, 16);
            sq += __shfl_xor_sync(0x0000ffffu, sq, 2, 16);
            sq += __shfl_xor_sync(0x0000ffffu, sq, 4, 16);
            sq += __shfl_xor_sync(0x0000ffffu, sq, 8, 16);
            float scale = sq / ((1.0f + sq) * sqrtf(sq + 1e-9f));
            float vcur = scale * s_u;
            if (it == 1) {
                float wn = vprev + vcur;          // b2 weights via linearity
                float whi = __shfl_down_sync(0x0000ffffu, wn, 1, 16);
                if ((tid & 1) == 0) {
                    unsigned int hw; F2H2(hw, wn, whi);
                    w_h[tid >> 1] = hw;
                }
            } else {
                outp[((size_t)b * C_SZ + c) * U_SZ + tid] = vcur;
            }
        }
        __syncthreads();
    }
}

// ---------------------------------------------------------------------------
extern "C" void kernel_launch(void* const* d_in, const int* in_sizes, int n_in,
                              void* d_out, int out_size)
{
    const float* x = (const float*)d_in[0];
    const float* W = (const float*)d_in[1];
    if (n_in >= 2 && in_sizes[0] == C_SZ * N_CAP * DIN * U_SZ &&
        in_sizes[1] == B_SZ * N_CAP * DIN) {
        const float* t = x; x = W; W = t;
    }

    const size_t smem2 =
        (size_t)(4 * 2304 + 128 + 8 + 8) * sizeof(float);   // 37,440B
    cudaFuncSetAttribute(k2_route, cudaFuncAttributeMaxDynamicSharedMemorySize,
                         (int)smem2);

    // k1 in two b-chunks (best measured k1 shape), then one full k2 that
    // reads b in reverse (freshest chunk first).
    for (int ch = 0; ch < B_SZ / B_CHUNK; ++ch) {
        const int bbase = ch * B_CHUNK;
        k1_uhat<<<dim3(N_CAP / 32, C_SZ, B_CHUNK / 32), 256>>>(
            x + (size_t)bbase * N_CAP * DIN, W, bbase);
    }
    k2_route<<<dim3(C_SZ, B_SZ), 256, smem2>>>((float*)d_out);
}

// round 14
// speedup vs baseline: 1.4251x; 1.0066x over previous
#include <cuda_runtime.h>
#include <cuda_fp16.h>
#include <cstdint>
#include <cstddef>

#define B_SZ    256
#define C_SZ    10
#define N_CAP   1152
#define DIN     8
#define U_SZ    16
#define B_CHUNK 128

// 94.4 MB fp16 scratch, layout [b][c][n][q]: per n a 32B row of 4 uint2
// (uint2 q = u-quad 4q..4q+3). Warp stores in k1 are 256B contiguous.
__device__ __align__(16) uint2 g_uhat2[(size_t)B_SZ * C_SZ * N_CAP * 4];

#define FFMA2(d, a, bb, cc) \
    asm("fma.rn.f32x2 %0, %1, %2, %3;" : "=l"(d) : "l"(a), "l"(bb), "l"(cc))
#define DUP2(d, s) \
    asm("mov.b64 %0, {%1, %1};" : "=l"(d) : "r"(s))
#define F2H2(d, lo, hi) \
    asm("cvt.rn.f16x2.f32 %0, %1, %2;" : "=r"(d) : "f"(hi), "f"(lo))

__device__ __forceinline__ __half2 u2h2(unsigned int v) { return *(__half2*)&v; }

// ---------------------------------------------------------------------------
// K1: u_hat -> fp16 [b][c][n][q], chunked over b.
// Grid (36, 10, B_CHUNK/32). 256 thr = 2 b-halves x 32 n x 4 u-quads.
// Identical compute to R13; only the store layout changed: warp = 32
// consecutive uint2 = 256B contiguous STG (2 wavefronts instead of 4).
// ---------------------------------------------------------------------------
__global__ __launch_bounds__(256) void k1_uhat(const float* __restrict__ x,
                                               const float* __restrict__ W,
                                               int bbase)
{
    __shared__ float xs[32 * 32 * 12];   // 48KB

    const int n0 = blockIdx.x * 32;
    const int c  = blockIdx.y;
    const int b0 = blockIdx.z * 32;      // local within chunk

    for (int t = threadIdx.x; t < 1024; t += 256) {
        const int b = t >> 5, n = t & 31;
        const float4* g = (const float4*)(x + ((size_t)(b0 + b) * N_CAP + (n0 + n)) * DIN);
        float4 v0 = g[0], v1 = g[1];
        float* d = xs + (b * 32 + n) * 12;
        *(float4*)(d)     = v0;
        *(float4*)(d + 4) = v1;
    }

    const int uq = threadIdx.x & 3;
    const int nl = (threadIdx.x >> 2) & 31;
    const int bl = threadIdx.x >> 7;     // 0..1
    const int n  = n0 + nl;

    unsigned long long wr[16];
    {
        const ulonglong2* Wp = (const ulonglong2*)(W + ((size_t)c * N_CAP + n) * 128);
        #pragma unroll
        for (int i = 0; i < 8; ++i) {
            ulonglong2 w = Wp[i * 4 + uq];
            wr[2 * i]     = w.x;     // u pair (4uq, 4uq+1)
            wr[2 * i + 1] = w.y;     // u pair (4uq+2, 4uq+3)
        }
    }
    __syncthreads();

    // [b][c][n][q] address in uint2 units: warp-contiguous.
    uint2* op = g_uhat2 +
        ((size_t)(bbase + b0 + bl * 16) * C_SZ + c) * ((size_t)N_CAP * 4)
        + (size_t)n * 4 + uq;

    #pragma unroll 4
    for (int s = 0; s < 16; ++s) {
        const int b = bl * 16 + s;
        const float* xp = xs + (b * 32 + nl) * 12;
        float4 xa = *(const float4*)(xp);
        float4 xb = *(const float4*)(xp + 4);

        unsigned long long x0, x1, x2, x3, x4, x5, x6, x7;
        DUP2(x0, __float_as_uint(xa.x));  DUP2(x1, __float_as_uint(xa.y));
        DUP2(x2, __float_as_uint(xa.z));  DUP2(x3, __float_as_uint(xa.w));
        DUP2(x4, __float_as_uint(xb.x));  DUP2(x5, __float_as_uint(xb.y));
        DUP2(x6, __float_as_uint(xb.z));  DUP2(x7, __float_as_uint(xb.w));

        unsigned long long a0 = 0ull, a1 = 0ull;
        FFMA2(a0, wr[0],  x0, a0);  FFMA2(a1, wr[1],  x0, a1);
        FFMA2(a0, wr[2],  x1, a0);  FFMA2(a1, wr[3],  x1, a1);
        FFMA2(a0, wr[4],  x2, a0);  FFMA2(a1, wr[5],  x2, a1);
        FFMA2(a0, wr[6],  x3, a0);  FFMA2(a1, wr[7],  x3, a1);
        FFMA2(a0, wr[8],  x4, a0);  FFMA2(a1, wr[9],  x4, a1);
        FFMA2(a0, wr[10], x5, a0);  FFMA2(a1, wr[11], x5, a1);
        FFMA2(a0, wr[12], x6, a0);  FFMA2(a1, wr[13], x6, a1);
        FFMA2(a0, wr[14], x7, a0);  FFMA2(a1, wr[15], x7, a1);

        unsigned int l0, h0, l1, h1;
        asm("mov.b64 {%0, %1}, %2;" : "=r"(l0), "=r"(h0) : "l"(a0));
        asm("mov.b64 {%0, %1}, %2;" : "=r"(l1), "=r"(h1) : "l"(a1));
        __half2 p0 = __floats2half2_rn(__uint_as_float(l0), __uint_as_float(h0));
        __half2 p1 = __floats2half2_rn(__uint_as_float(l1), __uint_as_float(h1));
        uint2 st;
        st.x = *(unsigned int*)&p0;
        st.y = *(unsigned int*)&p1;
        *op = st;
        op += (size_t)C_SZ * N_CAP * 4;
    }
}

// ---------------------------------------------------------------------------
__device__ __forceinline__ float blockReduceSum(float v, float* scratch)
{
    #pragma unroll
    for (int o = 16; o > 0; o >>= 1) v += __shfl_xor_sync(0xffffffffu, v, o);
    if ((threadIdx.x & 31) == 0) scratch[threadIdx.x >> 5] = v;
    __syncthreads();
    float r = 0.f;
    #pragma unroll
    for (int i = 0; i < 8; ++i) r += scratch[i];
    __syncthreads();
    return r;
}

// ---------------------------------------------------------------------------
// K2: routing per (b,c). Grid (C, B), 256 thr, 37.4KB smem, 5 CTAs/SM.
// b reversed (freshest L2 chunk first).
//  prologue: memcpy of the (b,c) slice (uint4 ldg -> XOR-swizzled STS.128,
//            conflict-free) with fused fp32 uniform-s0 (parity butterfly).
//  scan:     2x LDS.128 per n (swizzle p = u ^ ((u>>3)&1) -> conflict-free),
//            HFMA2 dot -> exp -> fp32 s-accum; butterfly; squash.
// ---------------------------------------------------------------------------
__global__ __launch_bounds__(256, 5) void k2_route(float* __restrict__ outp)
{
    extern __shared__ float sm[];
    unsigned int* uh  = (unsigned int*)sm;            // 2304 units x 16B
    float* red  = sm + 4 * 2304;                      // 128 (8 warps x 16 u)
    float* red2 = red + 128;                          // 8
    unsigned int* w_h = (unsigned int*)(red2 + 8);    // 8 words (16B aligned)

    const int tid = threadIdx.x;
    const int c   = blockIdx.x;
    const int b   = (B_SZ - 1) - blockIdx.y;          // reversed traversal
    const int w   = tid >> 5;
    const int g   = tid & 31;

    // ---- prologue: slice memcpy + fp32 uniform-s0 ----
    {
        const uint4* src = (const uint4*)(g_uhat2 +
                            ((size_t)b * C_SZ + c) * ((size_t)N_CAP * 4));
        float sa[8];
        #pragma unroll
        for (int j = 0; j < 8; ++j) sa[j] = 0.f;
        // 2304 uint4 units; unit m: n = m>>1, half h = m&1 (h = tid&1 fixed).
        for (int m = tid; m < N_CAP * 2; m += 256) {
            uint4 v = src[m];
            const int p = m ^ ((m >> 3) & 1);         // swizzle
            *(uint4*)(uh + 4 * p) = v;
            float2 f;
            f = __half22float2(u2h2(v.x)); sa[0] += f.x; sa[1] += f.y;
            f = __half22float2(u2h2(v.y)); sa[2] += f.x; sa[3] += f.y;
            f = __half22float2(u2h2(v.z)); sa[4] += f.x; sa[5] += f.y;
            f = __half22float2(u2h2(v.w)); sa[6] += f.x; sa[7] += f.y;
        }
        // parity-preserving butterfly: even lanes sum u0..7, odd u8..15
        #pragma unroll
        for (int o = 2; o <= 16; o <<= 1) {
            #pragma unroll
            for (int j = 0; j < 8; ++j)
                sa[j] += __shfl_xor_sync(0xffffffffu, sa[j], o);
        }
        if (g < 2) {
            #pragma unroll
            for (int j = 0; j < 8; ++j)
                red[w * 16 + g * 8 + j] = sa[j];
        }
    }
    __syncthreads();

    float vprev = 0.f;
    if (tid < 16) {
        float s_u = 0.f;
        #pragma unroll
        for (int ww = 0; ww < 8; ++ww) s_u += red[ww * 16 + tid];
        s_u *= (1.0f / (float)N_CAP);
        float sq = s_u * s_u;
        sq += __shfl_xor_sync(0x0000ffffu, sq, 1, 16);
        sq += __shfl_xor_sync(0x0000ffffu, sq, 2, 16);
        sq += __shfl_xor_sync(0x0000ffffu, sq, 4, 16);
        sq += __shfl_xor_sync(0x0000ffffu, sq, 8, 16);
        float scale = sq / ((1.0f + sq) * sqrtf(sq + 1e-9f));
        vprev = scale * s_u;                     // v0, u = tid
        float vhi = __shfl_down_sync(0x0000ffffu, vprev, 1, 16);
        if ((tid & 1) == 0) {
            unsigned int hw; F2H2(hw, vprev, vhi);
            w_h[tid >> 1] = hw;                  // w_h[j] = (v_2j, v_2j+1)
        }
    }
    __syncthreads();

    #pragma unroll
    for (int it = 1; it < 3; ++it) {
        uint4 wA = *(const uint4*)(w_h);
        uint4 wB = *(const uint4*)(w_h + 4);
        const __half2 w0 = u2h2(wA.x), w1 = u2h2(wA.y);
        const __half2 w2 = u2h2(wA.z), w3 = u2h2(wA.w);
        const __half2 w4 = u2h2(wB.x), w5 = u2h2(wB.y);
        const __half2 w6 = u2h2(wB.z), w7 = u2h2(wB.w);
        const __half2 z = __float2half2_rn(0.f);

        float acc[16];
        #pragma unroll
        for (int u = 0; u < 16; ++u) acc[u] = 0.f;
        float ls = 0.f;

        // ---- fused scan: 2 LDS.128 -> HFMA2 dot -> exp -> fp32 s-accum ----
        for (int n = tid; n < N_CAP; n += 256) {
            const int u0 = n << 1;
            const int p0 = u0 ^ ((u0 >> 3) & 1);
            const int p1 = (u0 + 1) ^ (((u0 + 1) >> 3) & 1);
            uint4 A  = *(const uint4*)(uh + 4 * p0);   // pairs 0..3
            uint4 Bv = *(const uint4*)(uh + 4 * p1);   // pairs 4..7

            __half2 aa = __hfma2(u2h2(A.x), w0, z);
            aa = __hfma2(u2h2(A.y), w1, aa);
            aa = __hfma2(u2h2(A.z), w2, aa);
            aa = __hfma2(u2h2(A.w), w3, aa);
            __half2 ac = __hfma2(u2h2(Bv.x), w4, z);
            ac = __hfma2(u2h2(Bv.y), w5, ac);
            ac = __hfma2(u2h2(Bv.z), w6, ac);
            ac = __hfma2(u2h2(Bv.w), w7, ac);
            float dot = (__low2float(aa) + __high2float(aa))
                      + (__low2float(ac) + __high2float(ac));
            float e = __expf(dot);
            ls += e;

            float2 v;
            v = __half22float2(u2h2(A.x));
            acc[0]  = fmaf(e, v.x, acc[0]);   acc[1]  = fmaf(e, v.y, acc[1]);
            v = __half22float2(u2h2(A.y));
            acc[2]  = fmaf(e, v.x, acc[2]);   acc[3]  = fmaf(e, v.y, acc[3]);
            v = __half22float2(u2h2(A.z));
            acc[4]  = fmaf(e, v.x, acc[4]);   acc[5]  = fmaf(e, v.y, acc[5]);
            v = __half22float2(u2h2(A.w));
            acc[6]  = fmaf(e, v.x, acc[6]);   acc[7]  = fmaf(e, v.y, acc[7]);
            v = __half22float2(u2h2(Bv.x));
            acc[8]  = fmaf(e, v.x, acc[8]);   acc[9]  = fmaf(e, v.y, acc[9]);
            v = __half22float2(u2h2(Bv.y));
            acc[10] = fmaf(e, v.x, acc[10]);  acc[11] = fmaf(e, v.y, acc[11]);
            v = __half22float2(u2h2(Bv.z));
            acc[12] = fmaf(e, v.x, acc[12]);  acc[13] = fmaf(e, v.y, acc[13]);
            v = __half22float2(u2h2(Bv.w));
            acc[14] = fmaf(e, v.x, acc[14]);  acc[15] = fmaf(e, v.y, acc[15]);
        }

        // ---- vector-halving butterfly: 16 accums over warp ----
        #pragma unroll
        for (int k = 0; k < 4; ++k) {
            const int o = 1 << k;
            const int h = 8 >> k;
            const bool hi = (g >> k) & 1;
            #pragma unroll
            for (int j = 0; j < h; ++j) {
                float send = hi ? acc[j] : acc[j + h];
                float r = __shfl_xor_sync(0xffffffffu, send, o);
                acc[j] = (hi ? acc[j + h] : acc[j]) + r;
            }
        }
        acc[0] += __shfl_xor_sync(0xffffffffu, acc[0], 16);
        const int u_own = ((g & 1) << 3) | (((g >> 1) & 1) << 2)
                        | (((g >> 2) & 1) << 1) | ((g >> 3) & 1);
        if (g < 16) red[w * 16 + u_own] = acc[0];

        float inv = 1.0f / blockReduceSum(ls, red2);  // syncs publish red

        // ---- squash (u = tid) ----
        if (tid < 16) {
            float s_u = 0.f;
            #pragma unroll
            for (int ww = 0; ww < 8; ++ww) s_u += red[ww * 16 + tid];
            s_u *= inv;
            float sq = s_u * s_u;
            sq += __shfl_xor_sync(0x0000ffffu, sq, 1, 16);
            sq += __shfl_xor_sync(0x0000ffffu, sq, 2, 16);
            sq += __shfl_xor_sync(0x0000ffffu, sq, 4, 16);
            sq += __shfl_xor_sync(0x0000ffffu, sq, 8, 16);
            float scale = sq / ((1.0f + sq) * sqrtf(sq + 1e-9f));
            float vcur = scale * s_u;
            if (it == 1) {
                float wn = vprev + vcur;          // b2 weights via linearity
                float whi = __shfl_down_sync(0x0000ffffu, wn, 1, 16);
                if ((tid & 1) == 0) {
                    unsigned int hw; F2H2(hw, wn, whi);
                    w_h[tid >> 1] = hw;
                }
            } else {
                outp[((size_t)b * C_SZ + c) * U_SZ + tid] = vcur;
            }
        }
        __syncthreads();
    }
}

// ---------------------------------------------------------------------------
extern "C" void kernel_launch(void* const* d_in, const int* in_sizes, int n_in,
                              void* d_out, int out_size)
{
    const float* x = (const float*)d_in[0];
    const float* W = (const float*)d_in[1];
    if (n_in >= 2 && in_sizes[0] == C_SZ * N_CAP * DIN * U_SZ &&
        in_sizes[1] == B_SZ * N_CAP * DIN) {
        const float* t = x; x = W; W = t;
    }

    const size_t smem2 =
        (size_t)(4 * 2304 + 128 + 8 + 8) * sizeof(float);   // 37,440B
    cudaFuncSetAttribute(k2_route, cudaFuncAttributeMaxDynamicSharedMemorySize,
                         (int)smem2);

    for (int ch = 0; ch < B_SZ / B_CHUNK; ++ch) {
        const int bbase = ch * B_CHUNK;
        k1_uhat<<<dim3(N_CAP / 32, C_SZ, B_CHUNK / 32), 256>>>(
            x + (size_t)bbase * N_CAP * DIN, W, bbase);
    }
    k2_route<<<dim3(C_SZ, B_SZ), 256, smem2>>>((float*)d_out);
}